// round 11
// baseline (speedup 1.0000x reference)
#include <cuda_runtime.h>
#include <cuda_bf16.h>
#include <math.h>
#include <stdint.h>

#define NM 10000
#define ND 552
#define LDA 560          // padded row length of augmented matrix (553 cols used)
#define NB 32
#define NPANEL 18        // 17*32 + 8 = 552
#define KSB 8            // k-split for F @ P
#define NCHUNK 313       // ceil(10000/32)

// ---------------- device scratch (static; no allocation allowed) ----------------
__device__ float          g_Pt[(size_t)ND * NM];           // 22.1 MB  P transposed [j][m]
__device__ __nv_bfloat16  g_Fhi[(size_t)ND * NM];          // 11 MB
__device__ __nv_bfloat16  g_Flo[(size_t)ND * NM];          // 11 MB
__device__ float          g_Bpart[(size_t)KSB * ND * ND];  // 9.8 MB
__device__ float          g_Aaug[(size_t)ND * LDA];        // [A | r] -> LU factors
__device__ float          g_rorig[ND];
__device__ float          g_tmp[ND];                       // x0 then x1
__device__ int            g_piv[ND];
__device__ float          g_ld[1];
__device__ float          g_y[NM];
__device__ float          g_z[NM];
__device__ float          g_resid[ND];

// ===================== helpers ==================
__device__ __forceinline__ uint32_t smem_u32(const void* p) {
    uint32_t a;
    asm("{ .reg .u64 t; cvta.to.shared.u64 t, %1; cvt.u32.u64 %0, t; }" : "=r"(a) : "l"(p));
    return a;
}

__device__ __forceinline__ void ldx4(uint32_t* r, uint32_t addr) {
    asm volatile("ldmatrix.sync.aligned.m8n8.x4.shared.b16 {%0,%1,%2,%3}, [%4];"
                 : "=r"(r[0]), "=r"(r[1]), "=r"(r[2]), "=r"(r[3]) : "r"(addr));
}

__device__ __forceinline__ void mma16816(float* c, const uint32_t* a, uint32_t b0, uint32_t b1) {
    asm volatile(
        "mma.sync.aligned.m16n8k16.row.col.f32.bf16.bf16.f32 "
        "{%0,%1,%2,%3}, {%4,%5,%6,%7}, {%8,%9}, {%0,%1,%2,%3};"
        : "+f"(c[0]), "+f"(c[1]), "+f"(c[2]), "+f"(c[3])
        : "r"(a[0]), "r"(a[1]), "r"(a[2]), "r"(a[3]), "r"(b0), "r"(b1));
}

__device__ __forceinline__ void split2(float a, float b, uint32_t& hv, uint32_t& lv) {
    __nv_bfloat16 ha = __float2bfloat16(a), hb = __float2bfloat16(b);
    __nv_bfloat162 hh; hh.x = ha; hh.y = hb;
    hv = *(uint32_t*)&hh;
    __nv_bfloat162 ll;
    ll.x = __float2bfloat16(a - __bfloat162float(ha));
    ll.y = __float2bfloat16(b - __bfloat162float(hb));
    lv = *(uint32_t*)&ll;
}

__device__ __forceinline__ void cpasync16(uint32_t dst, const void* src, bool pred) {
    int sz = pred ? 16 : 0;
    asm volatile("cp.async.cg.shared.global [%0], [%1], 16, %2;"
                 :: "r"(dst), "l"(src), "r"(sz) : "memory");
}
#define CP_COMMIT() asm volatile("cp.async.commit_group;" ::: "memory")
#define CP_WAIT1()  asm volatile("cp.async.wait_group 1;" ::: "memory")

// per-stage layout (bytes): Ahi 0, Alo 10240, Bhi 20480, Blo 30720; stage stride 40960
#define PSTG 40960

// kBmma static layout
#define SM_BYTES 40960
#define A_LO_OFF 10240
#define B_HI_OFF 20480
#define B_LO_OFF 30720

// ============================ F -> bf16 hi/lo split ==========================
__global__ void kFsplit(const float* __restrict__ F) {
    int idx = blockIdx.x * 256 + threadIdx.x;
    if (idx >= ND * NM) return;
    float f = F[idx];
    __nv_bfloat16 h = __float2bfloat16(f);
    g_Fhi[idx] = h;
    g_Flo[idx] = __float2bfloat16(f - __bfloat162float(h));
}

// =====================================================================
// kPmma: Pt[j][m] = (s2*exp(c*D)) @ F^T, bf16-split 3-pass mma.sync,
// 2-stage double-buffered smem, cp.async for F, register prefetch for D.
// grid (79 m-tiles of 128, 5 j-tiles of 128), 256 threads.
// =====================================================================
__global__ __launch_bounds__(256, 1) void kPmma(const float* __restrict__ Dm,
                                                const float* __restrict__ lsp,
                                                const float* __restrict__ sgp) {
    extern __shared__ __align__(16) char sm[];
    const uint32_t sb = smem_u32(sm);

    const int tid = threadIdx.x, lane = tid & 31, wid = tid >> 5;
    const int m0 = blockIdx.x * 128, j0 = blockIdx.y * 128;

    const float l = lsp[0];
    const float cexp = -0.5f / (l * l);
    const float s2 = sgp[0] * sgp[0];

    // loader mapping: thread t owns row lr = t>>1, 16-k-group lk = (t&1)*16
    const int lr = tid >> 1, lk = (tid & 1) * 16;
    const bool mval = (m0 + lr) < NM;
    const bool nval = (j0 + lr) < ND;
    const int jrow = nval ? (j0 + lr) : (ND - 1);
    const float* Dp = Dm + (size_t)(m0 + lr) * NM + lk;
    const __nv_bfloat16* Fh = g_Fhi + (size_t)jrow * NM + lk;
    const __nv_bfloat16* Fl = g_Flo + (size_t)jrow * NM + lk;

    const uint32_t sA = (uint32_t)(lr * 40 + lk) * 2;   // byte offset within array

    float4 dv[4];
    bool dok[4];

#define LOADD(ch)                                                             \
    {                                                                         \
        int _k0 = (ch) * 32;                                                  \
        _Pragma("unroll")                                                     \
        for (int i = 0; i < 4; i++) {                                         \
            int kk = _k0 + lk + i * 4;                                        \
            dok[i] = mval && (kk < NM);                                       \
            dv[i] = dok[i] ? *(const float4*)(Dp + _k0 + i * 4)               \
                           : make_float4(0.f, 0.f, 0.f, 0.f);                 \
        }                                                                     \
    }

// BUGFIX vs R10: each thread owns 16 bf16 (32 bytes) per array; issue TWO
// 16-byte cp.async per array (the missing +16B half caused the NaN).
#define ISSUEF(ch, s)                                                         \
    {                                                                         \
        int _k0 = (ch) * 32;                                                  \
        bool ok  = nval && (_k0 + lk < NM);                                   \
        bool ok2 = nval && (_k0 + lk + 8 < NM);                               \
        uint32_t dB = sb + (s) * PSTG + 20480 + sA;                           \
        cpasync16(dB,              Fh + _k0,     ok);                         \
        cpasync16(dB + 16,         Fh + _k0 + 8, ok2);                        \
        cpasync16(dB + 10240,      Fl + _k0,     ok);                         \
        cpasync16(dB + 10240 + 16, Fl + _k0 + 8, ok2);                        \
    }

#define STSA(s)                                                               \
    {                                                                         \
        char* stg = sm + (s) * PSTG;                                          \
        _Pragma("unroll")                                                     \
        for (int i = 0; i < 4; i++) {                                         \
            float e0 = dok[i] ? s2 * __expf(cexp * dv[i].x) : 0.f;            \
            float e1 = dok[i] ? s2 * __expf(cexp * dv[i].y) : 0.f;            \
            float e2 = dok[i] ? s2 * __expf(cexp * dv[i].z) : 0.f;            \
            float e3 = dok[i] ? s2 * __expf(cexp * dv[i].w) : 0.f;            \
            uint32_t h01, l01, h23, l23;                                      \
            split2(e0, e1, h01, l01);                                         \
            split2(e2, e3, h23, l23);                                         \
            *(uint2*)(stg + sA + i * 8)         = make_uint2(h01, h23);       \
            *(uint2*)(stg + 10240 + sA + i * 8) = make_uint2(l01, l23);       \
        }                                                                     \
    }

    // warp tiling: 4 m-warps x 2 n-warps; warp tile 32m x 64n
    const int wm = (wid & 3) * 32, wn = (wid >> 2) * 64;
    const uint32_t aAoff = (uint32_t)((wm + (lane & 15)) * 40 + ((lane >> 4) & 1) * 8) * 2;
    const uint32_t aBoff = (uint32_t)((wn + ((lane >> 4) << 3) + (lane & 7)) * 40
                                      + ((lane >> 3) & 1) * 8) * 2;

    float acc[2][8][4];
#pragma unroll
    for (int a = 0; a < 2; a++)
#pragma unroll
        for (int b = 0; b < 8; b++)
#pragma unroll
            for (int d = 0; d < 4; d++) acc[a][b][d] = 0.f;

    // prologue
    LOADD(0);
    ISSUEF(0, 0); CP_COMMIT();
    STSA(0);
    LOADD(1);
    ISSUEF(1, 1); CP_COMMIT();
    CP_WAIT1();
    __syncthreads();                 // stage 0 ready

    for (int ch = 0; ch < NCHUNK; ++ch) {
        const int s = ch & 1;
        const uint32_t base = sb + s * PSTG;

        // ---- compute stage s (2 k-steps of 16) ----
#pragma unroll
        for (int kst = 0; kst < 2; ++kst) {
            uint32_t ah[2][4], al[2][4];
#pragma unroll
            for (int mt = 0; mt < 2; ++mt) {
                uint32_t o = aAoff + mt * 1280 + kst * 32;
                ldx4(ah[mt], base + o);
                ldx4(al[mt], base + 10240 + o);
            }
#pragma unroll
            for (int nh = 0; nh < 2; ++nh) {
                uint32_t bh[2][4], bl[2][4];
#pragma unroll
                for (int ng = 0; ng < 2; ++ng) {
                    uint32_t o = aBoff + nh * 2560 + ng * 1280 + kst * 32;
                    ldx4(bh[ng], base + 20480 + o);
                    ldx4(bl[ng], base + 30720 + o);
                }
#pragma unroll
                for (int mt = 0; mt < 2; mt++)
#pragma unroll
                    for (int nt = 0; nt < 4; nt++) {
                        float* cc = acc[mt][nh * 4 + nt];
                        uint32_t b0h = bh[nt >> 1][(nt & 1) * 2];
                        uint32_t b1h = bh[nt >> 1][(nt & 1) * 2 + 1];
                        uint32_t b0l = bl[nt >> 1][(nt & 1) * 2];
                        uint32_t b1l = bl[nt >> 1][(nt & 1) * 2 + 1];
                        mma16816(cc, ah[mt], b0h, b1h);
                        mma16816(cc, ah[mt], b0l, b1l);
                        mma16816(cc, al[mt], b0h, b1h);
                    }
            }
        }
        __syncthreads();             // done reading stage s

        if (ch + 2 < NCHUNK) ISSUEF(ch + 2, s);
        CP_COMMIT();
        if (ch + 1 < NCHUNK) STSA(s ^ 1);
        if (ch + 2 < NCHUNK) LOADD(ch + 2);
        CP_WAIT1();                  // F for stage s^1 landed
        __syncthreads();             // stage s^1 ready
    }

    // ---- epilogue: transpose via smem staging (reuse stage 0), coalesced in m ----
    float* stg = (float*)sm;  // [128 n][68 m] per 64-m half
#pragma unroll
    for (int h = 0; h < 2; ++h) {
        __syncthreads();
        if (((wid & 3) >> 1) == h) {
            const int rb = wm - h * 64 + (lane >> 2);
            const int cb = 2 * (lane & 3);
#pragma unroll
            for (int mt = 0; mt < 2; mt++)
#pragma unroll
                for (int nt = 0; nt < 8; nt++) {
                    int r = rb + mt * 16;
                    int c = wn + ((nt >> 2) * 32) + ((nt & 3) * 8) + cb;
                    stg[(c + 0) * 68 + r]     = acc[mt][nt][0];
                    stg[(c + 1) * 68 + r]     = acc[mt][nt][1];
                    stg[(c + 0) * 68 + r + 8] = acc[mt][nt][2];
                    stg[(c + 1) * 68 + r + 8] = acc[mt][nt][3];
                }
        }
        __syncthreads();
#pragma unroll 4
        for (int it = 0; it < 32; ++it) {
            int nr = it * 4 + (tid >> 6);
            int mc = tid & 63;
            int j = j0 + nr, m = m0 + h * 64 + mc;
            if (j < ND && m < NM) g_Pt[(size_t)j * NM + m] = stg[nr * 68 + mc];
        }
    }
}

// =====================================================================
// kBmma: Bpart[z] = F @ P   (A = F hi/lo, B = Pt split on the fly)
// =====================================================================
__global__ __launch_bounds__(256, 1) void kBmma() {
    __shared__ __align__(16) char sm[SM_BYTES];
    __nv_bfloat16* Ahi = (__nv_bfloat16*)sm;
    __nv_bfloat16* Alo = (__nv_bfloat16*)(sm + A_LO_OFF);
    __nv_bfloat16* Bhi = (__nv_bfloat16*)(sm + B_HI_OFF);
    __nv_bfloat16* Blo = (__nv_bfloat16*)(sm + B_LO_OFF);
    const uint32_t sb = smem_u32(sm);

    const int tid = threadIdx.x, lane = tid & 31, wid = tid >> 5;
    const int i0 = blockIdx.x * 128, j0 = blockIdx.y * 128;
    const int z = blockIdx.z;
    const int c0 = z * 40;
    const int c1 = min(NCHUNK, c0 + 40);

    const int lr = tid >> 1, lk = (tid & 1) * 16;
    const bool ival = (i0 + lr) < ND;
    const bool jval = (j0 + lr) < ND;
    const __nv_bfloat16* Fh = g_Fhi + (size_t)(i0 + lr) * NM + lk;
    const __nv_bfloat16* Fl = g_Flo + (size_t)(i0 + lr) * NM + lk;
    const float* Pp = g_Pt + (size_t)(j0 + lr) * NM + lk;

    float4 pv[4];
    bool pok[4];
    uint4 fh[2], fl[2];

#define LOADCH_B(k0)                                                          \
    {                                                                         \
        _Pragma("unroll")                                                     \
        for (int i = 0; i < 2; i++) {                                         \
            int kk = (k0) + lk + i * 8;                                       \
            bool ok = ival && (kk < NM);                                      \
            fh[i] = ok ? *(const uint4*)(Fh + (k0) + i * 8) : make_uint4(0, 0, 0, 0); \
            fl[i] = ok ? *(const uint4*)(Fl + (k0) + i * 8) : make_uint4(0, 0, 0, 0); \
        }                                                                     \
        _Pragma("unroll")                                                     \
        for (int i = 0; i < 4; i++) {                                         \
            int kk = (k0) + lk + i * 4;                                       \
            pok[i] = jval && (kk < NM);                                       \
            pv[i] = pok[i] ? *(const float4*)(Pp + (k0) + i * 4)              \
                           : make_float4(0.f, 0.f, 0.f, 0.f);                 \
        }                                                                     \
    }

    const int sA = lr * 40 + lk;
    const int wm = (wid & 3) * 32, wn = (wid >> 2) * 64;
    const uint32_t aAoff = (uint32_t)((wm + (lane & 15)) * 40 + ((lane >> 4) & 1) * 8) * 2;
    const uint32_t aBoff = (uint32_t)((wn + ((lane >> 4) << 3) + (lane & 7)) * 40
                                      + ((lane >> 3) & 1) * 8) * 2;

    float acc[2][8][4];
#pragma unroll
    for (int a = 0; a < 2; a++)
#pragma unroll
        for (int b = 0; b < 8; b++)
#pragma unroll
            for (int d = 0; d < 4; d++) acc[a][b][d] = 0.f;

    LOADCH_B(c0 * 32);

    for (int ch = c0; ch < c1; ++ch) {
        *(uint4*)(Ahi + sA) = fh[0];
        *(uint4*)(Ahi + sA + 8) = fh[1];
        *(uint4*)(Alo + sA) = fl[0];
        *(uint4*)(Alo + sA + 8) = fl[1];
#pragma unroll
        for (int i = 0; i < 4; i++) {
            uint32_t h01, l01, h23, l23;
            split2(pv[i].x, pv[i].y, h01, l01);
            split2(pv[i].z, pv[i].w, h23, l23);
            *(uint2*)(Bhi + sA + i * 4) = make_uint2(h01, h23);
            *(uint2*)(Blo + sA + i * 4) = make_uint2(l01, l23);
        }
        __syncthreads();

        if (ch + 1 < c1) LOADCH_B((ch + 1) * 32);

#pragma unroll
        for (int kst = 0; kst < 2; ++kst) {
            uint32_t ah[2][4], al[2][4];
#pragma unroll
            for (int mt = 0; mt < 2; ++mt) {
                uint32_t o = aAoff + mt * 1280 + kst * 32;
                ldx4(ah[mt], sb + o);
                ldx4(al[mt], sb + A_LO_OFF + o);
            }
#pragma unroll
            for (int nh = 0; nh < 2; ++nh) {
                uint32_t bh[2][4], bl[2][4];
#pragma unroll
                for (int ng = 0; ng < 2; ++ng) {
                    uint32_t o = aBoff + nh * 2560 + ng * 1280 + kst * 32;
                    ldx4(bh[ng], sb + B_HI_OFF + o);
                    ldx4(bl[ng], sb + B_LO_OFF + o);
                }
#pragma unroll
                for (int mt = 0; mt < 2; mt++)
#pragma unroll
                    for (int nt = 0; nt < 4; nt++) {
                        float* cc = acc[mt][nh * 4 + nt];
                        uint32_t b0h = bh[nt >> 1][(nt & 1) * 2];
                        uint32_t b1h = bh[nt >> 1][(nt & 1) * 2 + 1];
                        uint32_t b0l = bl[nt >> 1][(nt & 1) * 2];
                        uint32_t b1l = bl[nt >> 1][(nt & 1) * 2 + 1];
                        mma16816(cc, ah[mt], b0h, b1h);
                        mma16816(cc, ah[mt], b0l, b1l);
                        mma16816(cc, al[mt], b0h, b1h);
                    }
            }
        }
        __syncthreads();
    }

    float* Bp = g_Bpart + (size_t)z * ND * ND;
    const int rb = i0 + wm + (lane >> 2);
    const int cb = j0 + wn + 2 * (lane & 3);
#pragma unroll
    for (int mt = 0; mt < 2; mt++)
#pragma unroll
        for (int nt = 0; nt < 8; nt++) {
            int i = rb + mt * 16;
            int c = cb + (nt >> 2) * 32 + (nt & 3) * 8;
            if (c < ND) {
                if (i < ND)
                    *(float2*)(Bp + (size_t)i * ND + c) = make_float2(acc[mt][nt][0], acc[mt][nt][1]);
                if (i + 8 < ND)
                    *(float2*)(Bp + (size_t)(i + 8) * ND + c) = make_float2(acc[mt][nt][2], acc[mt][nt][3]);
            }
        }
}

// combine k-split partials + data_cov into Aaug columns [0, 552)
__global__ void kC(const float* __restrict__ dcov) {
    int idx = blockIdx.x * 256 + threadIdx.x;
    if (idx >= ND * ND) return;
    float s = dcov[idx];
#pragma unroll
    for (int zz = 0; zz < KSB; zz++) s += g_Bpart[(size_t)zz * ND * ND + idx];
    int i = idx / ND, j = idx - i * ND;
    g_Aaug[i * LDA + j] = s;
}

// prior misfit r = d_obs - m0 * rowsum(F)
__global__ __launch_bounds__(256) void kR(const float* __restrict__ F,
                                          const float* __restrict__ dobs,
                                          const float* __restrict__ m0p) {
    __shared__ float red[8];
    const int i = blockIdx.x;
    const float* row = F + (size_t)i * NM;
    float s = 0.f;
    for (int t = threadIdx.x; t < NM; t += 256) s += row[t];
#pragma unroll
    for (int o = 16; o; o >>= 1) s += __shfl_down_sync(0xffffffffu, s, o);
    if ((threadIdx.x & 31) == 0) red[threadIdx.x >> 5] = s;
    __syncthreads();
    if (threadIdx.x == 0) {
        float tot = 0.f;
#pragma unroll
        for (int w = 0; w < 8; w++) tot += red[w];
        float r = dobs[i] - m0p[0] * tot;
        g_Aaug[i * LDA + ND] = r;
        g_rorig[i] = r;
    }
}

// =====================================================================
// LU panel factorization with partial pivoting; FULL row swaps + pivot record
// =====================================================================
__global__ __launch_bounds__(512) void kLU(int p0, int pw) {
    extern __shared__ float sp[];
    const int tid = threadIdx.x;
    const int nrows = ND - p0;

    for (int idx = tid; idx < nrows * pw; idx += 512)
        sp[idx] = g_Aaug[(p0 + idx / pw) * LDA + p0 + (idx % pw)];
    __syncthreads();

    __shared__ float redv[16];
    __shared__ int   redi[16];
    __shared__ int   s_piv;
    __shared__ float s_pv;

    for (int j = 0; j < pw; j++) {
        float best = -1.f; int bi = j;
        for (int i = j + tid; i < nrows; i += 512) {
            float v = fabsf(sp[i * pw + j]);
            if (v > best) { best = v; bi = i; }
        }
#pragma unroll
        for (int o = 16; o; o >>= 1) {
            float ov = __shfl_down_sync(0xffffffffu, best, o);
            int   oi = __shfl_down_sync(0xffffffffu, bi,   o);
            if (ov > best) { best = ov; bi = oi; }
        }
        if ((tid & 31) == 0) { redv[tid >> 5] = best; redi[tid >> 5] = bi; }
        __syncthreads();
        if (tid < 32) {
            float b2 = (tid < 16) ? redv[tid] : -1.f;
            int   i2 = (tid < 16) ? redi[tid] : j;
#pragma unroll
            for (int o = 8; o; o >>= 1) {
                float ov = __shfl_down_sync(0xffffffffu, b2, o);
                int   oi = __shfl_down_sync(0xffffffffu, i2, o);
                if (ov > b2) { b2 = ov; i2 = oi; }
            }
            if (tid == 0) { s_piv = i2; s_pv = sp[i2 * pw + j]; g_piv[p0 + j] = p0 + i2; }
        }
        __syncthreads();
        const int piv = s_piv;
        const float pv = s_pv;

        if (piv != j) {
            if (tid < pw) {
                float t = sp[j * pw + tid];
                sp[j * pw + tid] = sp[piv * pw + tid];
                sp[piv * pw + tid] = t;
            }
            const int gr1 = (p0 + j) * LDA, gr2 = (p0 + piv) * LDA;
            for (int cc = tid; cc < p0; cc += 512) {          // earlier L columns
                float t1 = g_Aaug[gr1 + cc];
                g_Aaug[gr1 + cc] = g_Aaug[gr2 + cc];
                g_Aaug[gr2 + cc] = t1;
            }
            for (int cc = p0 + pw + tid; cc <= ND; cc += 512) { // trailing incl. rhs
                float t1 = g_Aaug[gr1 + cc];
                g_Aaug[gr1 + cc] = g_Aaug[gr2 + cc];
                g_Aaug[gr2 + cc] = t1;
            }
        }
        __syncthreads();

        const float inv = 1.f / pv;
        for (int i = j + 1 + tid; i < nrows; i += 512) {
            float lij = sp[i * pw + j] * inv;
            sp[i * pw + j] = lij;
            for (int jj = j + 1; jj < pw; jj++)
                sp[i * pw + jj] -= lij * sp[j * pw + jj];
        }
        __syncthreads();
    }

    for (int idx = tid; idx < nrows * pw; idx += 512)
        g_Aaug[(p0 + idx / pw) * LDA + p0 + (idx % pw)] = sp[idx];
}

__global__ __launch_bounds__(128) void kTRSM(int p0, int pw) {
    __shared__ float Ls[32][33];
    const int tid = threadIdx.x;
    for (int idx = tid; idx < 32 * 33; idx += 128) ((float*)Ls)[idx] = 0.f;
    __syncthreads();
    for (int idx = tid; idx < pw * pw; idx += 128)
        Ls[idx / pw][idx % pw] = g_Aaug[(p0 + idx / pw) * LDA + p0 + (idx % pw)];
    __syncthreads();

    const int cc = p0 + pw + blockIdx.x * 128 + tid;
    if (cc > ND) return;

    float v[32];
#pragma unroll
    for (int i = 0; i < 32; i++) v[i] = (i < pw) ? g_Aaug[(p0 + i) * LDA + cc] : 0.f;
#pragma unroll
    for (int k = 0; k < 32; k++) {
        if (k >= pw) break;
        float vk = v[k];
#pragma unroll
        for (int i = 0; i < 32; i++)
            if (i > k) v[i] -= Ls[i][k] * vk;
    }
#pragma unroll
    for (int i = 0; i < 32; i++)
        if (i < pw) g_Aaug[(p0 + i) * LDA + cc] = v[i];
}

__global__ __launch_bounds__(256) void kG(int p0, int pw) {
    __shared__ float Ls[32][33];
    __shared__ float Us[32][36];
    const int tid = threadIdx.x;
    const int r0  = p0 + pw;
    const int gi0 = r0 + blockIdx.x * 32;
    const int gj0 = r0 + blockIdx.y * 32;

    for (int idx = tid; idx < 32 * 32; idx += 256) {
        int i = idx >> 5, k = idx & 31;
        float v = 0.f;
        if (k < pw && gi0 + i < ND) v = g_Aaug[(gi0 + i) * LDA + p0 + k];
        Ls[i][k] = v;
    }
    for (int idx = tid; idx < 32 * 32; idx += 256) {
        int k = idx >> 5, jn = idx & 31;
        float v = 0.f;
        if (k < pw && gj0 + jn <= ND) v = g_Aaug[(p0 + k) * LDA + gj0 + jn];
        Us[k][jn] = v;
    }
    __syncthreads();

    const int mi = tid >> 3;
    const int nj = (tid & 7) * 4;
    float a0 = 0.f, a1 = 0.f, a2 = 0.f, a3 = 0.f;
    for (int k = 0; k < pw; k++) {
        float a = Ls[mi][k];
        a0 += a * Us[k][nj + 0];
        a1 += a * Us[k][nj + 1];
        a2 += a * Us[k][nj + 2];
        a3 += a * Us[k][nj + 3];
    }
    const int gi = gi0 + mi;
    if (gi < ND) {
        if (gj0 + nj + 0 <= ND) g_Aaug[gi * LDA + gj0 + nj + 0] -= a0;
        if (gj0 + nj + 1 <= ND) g_Aaug[gi * LDA + gj0 + nj + 1] -= a1;
        if (gj0 + nj + 2 <= ND) g_Aaug[gi * LDA + gj0 + nj + 2] -= a2;
        if (gj0 + nj + 3 <= ND) g_Aaug[gi * LDA + gj0 + nj + 3] -= a3;
    }
}

// back-substitution of the augmented rhs -> x0; logdet -> g_ld
__global__ __launch_bounds__(576) void kBack(void) {
    __shared__ float x[ND];
    __shared__ float ub[32][33];
    __shared__ float red[18];
    const int tid = threadIdx.x;

    for (int i = tid; i < ND; i += 576) x[i] = g_Aaug[i * LDA + ND];
    float ld = 0.f;
    for (int k = tid; k < ND; k += 576) ld += logf(fabsf(g_Aaug[k * LDA + k]));
    __syncthreads();

    for (int pb = NPANEL - 1; pb >= 0; pb--) {
        const int p0 = pb * NB;
        const int pw = (pb == NPANEL - 1) ? (ND - p0) : NB;
        for (int idx = tid; idx < pw * pw; idx += 576)
            ub[idx / pw][idx % pw] = g_Aaug[(p0 + idx / pw) * LDA + p0 + (idx % pw)];
        __syncthreads();
        for (int j = pw - 1; j >= 0; j--) {
            if (tid == 0) x[p0 + j] = x[p0 + j] / ub[j][j];
            __syncthreads();
            float xk = x[p0 + j];
            if (tid < j) x[p0 + tid] -= ub[tid][j] * xk;
            __syncthreads();
        }
        for (int i = tid; i < p0; i += 576) {
            float s = 0.f;
            for (int j = 0; j < pw; j++) s += g_Aaug[i * LDA + p0 + j] * x[p0 + j];
            x[i] -= s;
        }
        __syncthreads();
    }

#pragma unroll
    for (int o = 16; o; o >>= 1) ld += __shfl_down_sync(0xffffffffu, ld, o);
    if ((tid & 31) == 0) red[tid >> 5] = ld;
    __syncthreads();
    if (tid == 0) {
        float tl = 0.f;
        for (int w = 0; w < 18; w++) tl += red[w];
        g_ld[0] = tl;
    }
    for (int i = tid; i < ND; i += 576) g_tmp[i] = x[i];
}

// ===================== iterative refinement: exact fp32 operator =============
// y = F^T x0
__global__ __launch_bounds__(256) void kAy(const float* __restrict__ F) {
    __shared__ float sx[ND];
    const int tid = threadIdx.x;
    for (int i = tid; i < ND; i += 256) sx[i] = g_tmp[i];
    __syncthreads();
    const int m = blockIdx.x * 256 + tid;
    if (m >= NM) return;
    float s = 0.f;
#pragma unroll 4
    for (int i = 0; i < ND; i++) s += F[(size_t)i * NM + m] * sx[i];
    g_y[m] = s;
}

// z = (s2 exp(cD)) @ y   (warp per row)
__global__ __launch_bounds__(256) void kAz(const float* __restrict__ Dm,
                                           const float* __restrict__ lsp,
                                           const float* __restrict__ sgp) {
    const int tid = threadIdx.x, lane = tid & 31, warp = tid >> 5;
    const int row = blockIdx.x * 8 + warp;
    if (row >= NM) return;
    const float l = lsp[0];
    const float c = -0.5f / (l * l);
    const float s2 = sgp[0] * sgp[0];
    const float* dr = Dm + (size_t)row * NM;
    float s = 0.f;
    for (int k = lane; k < NM; k += 32) s += __expf(c * dr[k]) * __ldg(&g_y[k]);
#pragma unroll
    for (int o = 16; o; o >>= 1) s += __shfl_down_sync(0xffffffffu, s, o);
    if (lane == 0) g_z[row] = s2 * s;
}

// resid = r - (dcov x0 + F z)
__global__ __launch_bounds__(256) void kAw(const float* __restrict__ F,
                                           const float* __restrict__ dcov) {
    __shared__ float red[8];
    const int i = blockIdx.x;
    const int tid = threadIdx.x;
    float s = 0.f;
    const float* fr = F + (size_t)i * NM;
    for (int m = tid; m < NM; m += 256) s += fr[m] * g_z[m];
    const float* cr = dcov + (size_t)i * ND;
    for (int j = tid; j < ND; j += 256) s += cr[j] * g_tmp[j];
#pragma unroll
    for (int o = 16; o; o >>= 1) s += __shfl_down_sync(0xffffffffu, s, o);
    if ((tid & 31) == 0) red[tid >> 5] = s;
    __syncthreads();
    if (tid == 0) {
        float tot = 0.f;
#pragma unroll
        for (int w = 0; w < 8; w++) tot += red[w];
        g_resid[i] = g_rorig[i] - tot;
    }
}

// solve LU dx = P resid; x1 = x0 + dx; out[0] = logdet + r^T x1; g_tmp = x1
__global__ __launch_bounds__(512) void kSolve(float* __restrict__ out) {
    __shared__ float x[ND];
    __shared__ float Bs[32][33];
    __shared__ float red[16];
    const int tid = threadIdx.x;

    for (int i = tid; i < ND; i += 512) x[i] = g_resid[i];
    __syncthreads();

    if (tid == 0) {
        for (int k = 0; k < ND; k++) {
            int pk = g_piv[k];
            if (pk != k) { float t = x[k]; x[k] = x[pk]; x[pk] = t; }
        }
    }
    __syncthreads();

    // forward: L (unit diag)
    for (int pb = 0; pb < NPANEL; pb++) {
        const int p0 = pb * NB;
        const int pw = (pb == NPANEL - 1) ? (ND - p0) : NB;
        for (int idx = tid; idx < pw * pw; idx += 512)
            Bs[idx / pw][idx % pw] = g_Aaug[(p0 + idx / pw) * LDA + p0 + (idx % pw)];
        __syncthreads();
        if (tid < 32) {
            float xi = (tid < pw) ? x[p0 + tid] : 0.f;
            for (int j = 0; j < pw; j++) {
                float xj = __shfl_sync(0xffffffffu, xi, j);
                if (tid > j && tid < pw) xi -= Bs[tid][j] * xj;
            }
            if (tid < pw) x[p0 + tid] = xi;
        }
        __syncthreads();
        for (int i = p0 + pw + tid; i < ND; i += 512) {
            float s = 0.f;
            for (int j = 0; j < pw; j++) s += g_Aaug[i * LDA + p0 + j] * x[p0 + j];
            x[i] -= s;
        }
        __syncthreads();
    }

    // backward: U
    for (int pb = NPANEL - 1; pb >= 0; pb--) {
        const int p0 = pb * NB;
        const int pw = (pb == NPANEL - 1) ? (ND - p0) : NB;
        for (int idx = tid; idx < pw * pw; idx += 512)
            Bs[idx / pw][idx % pw] = g_Aaug[(p0 + idx / pw) * LDA + p0 + (idx % pw)];
        __syncthreads();
        if (tid < 32) {
            float xi = (tid < pw) ? x[p0 + tid] : 0.f;
            for (int j = pw - 1; j >= 0; j--) {
                if (tid == j) xi = xi / Bs[j][j];
                float xj = __shfl_sync(0xffffffffu, xi, j);
                if (tid < j) xi -= Bs[tid][j] * xj;
            }
            if (tid < pw) x[p0 + tid] = xi;
        }
        __syncthreads();
        for (int i = tid; i < p0; i += 512) {
            float s = 0.f;
            for (int j = 0; j < pw; j++) s += g_Aaug[i * LDA + p0 + j] * x[p0 + j];
            x[i] -= s;
        }
        __syncthreads();
    }

    // x1 = x0 + dx; dp = r^T x1
    float dp = 0.f;
    for (int i = tid; i < ND; i += 512) {
        float v = g_tmp[i] + x[i];
        x[i] = v;
        dp += g_rorig[i] * v;
    }
#pragma unroll
    for (int o = 16; o; o >>= 1) dp += __shfl_down_sync(0xffffffffu, dp, o);
    if ((tid & 31) == 0) red[tid >> 5] = dp;
    __syncthreads();
    if (tid == 0) {
        float td = 0.f;
#pragma unroll
        for (int w = 0; w < 16; w++) td += red[w];
        out[0] = g_ld[0] + td;
    }
    for (int i = tid; i < ND; i += 512) g_tmp[i] = x[i];
}

// m_posterior = m0 + P @ x1, via Pt (thread per model row, coalesced)
__global__ __launch_bounds__(256) void kM(float* __restrict__ out,
                                          const float* __restrict__ m0p) {
    __shared__ float sx[ND];
    const int tid = threadIdx.x;
    for (int i = tid; i < ND; i += 256) sx[i] = g_tmp[i];
    __syncthreads();
    const int m = blockIdx.x * 256 + tid;
    if (m >= NM) return;
    float s = 0.f;
#pragma unroll 4
    for (int j = 0; j < ND; j++) s += g_Pt[(size_t)j * NM + m] * sx[j];
    out[1 + m] = m0p[0] + s;
}

// =====================================================================
extern "C" void kernel_launch(void* const* d_in, const int* in_sizes, int n_in,
                              void* d_out, int out_size) {
    const float* D    = (const float*)d_in[0];
    const float* F    = (const float*)d_in[1];
    const float* dobs = (const float*)d_in[2];
    const float* dcov = (const float*)d_in[3];
    const float* m0p  = (const float*)d_in[4];
    const float* lsp  = (const float*)d_in[5];
    const float* sgp  = (const float*)d_in[6];
    float* out = (float*)d_out;

    cudaFuncSetAttribute(kLU, cudaFuncAttributeMaxDynamicSharedMemorySize, ND * NB * 4);
    cudaFuncSetAttribute(kPmma, cudaFuncAttributeMaxDynamicSharedMemorySize, 2 * PSTG);

    kFsplit<<<(ND * NM + 255) / 256, 256>>>(F);
    kPmma<<<dim3(79, 5), 256, 2 * PSTG>>>(D, lsp, sgp);
    kBmma<<<dim3(5, 5, KSB), 256>>>();
    kC<<<(ND * ND + 255) / 256, 256>>>(dcov);
    kR<<<ND, 256>>>(F, dobs, m0p);

    for (int p = 0; p < NPANEL; p++) {
        const int p0 = p * NB;
        const int pw = (p == NPANEL - 1) ? (ND - p0) : NB;
        const int nrows = ND - p0;
        kLU<<<1, 512, nrows * pw * 4>>>(p0, pw);
        const int tcols = ND + 1 - (p0 + pw);
        if (tcols > 0) kTRSM<<<(tcols + 127) / 128, 128>>>(p0, pw);
        const int m = ND - (p0 + pw);
        if (m > 0) kG<<<dim3((m + 31) / 32, (tcols + 31) / 32), 256>>>(p0, pw);
    }

    kBack<<<1, 576>>>();
    kAy<<<(NM + 255) / 256, 256>>>(F);
    kAz<<<(NM + 7) / 8, 256>>>(D, lsp, sgp);
    kAw<<<ND, 256>>>(F, dcov);
    kSolve<<<1, 512>>>(out);
    kM<<<(NM + 255) / 256, 256>>>(out, m0p);
}

// round 13
// speedup vs baseline: 1.0384x; 1.0384x over previous
#include <cuda_runtime.h>
#include <cuda_bf16.h>
#include <math.h>
#include <stdint.h>

#define NM 10000
#define ND 552
#define LDA 560          // padded row length of augmented matrix (553 cols used)
#define NB 32
#define NPANEL 18        // 17*32 + 8 = 552
#define KSB 8            // k-split for F @ P
#define NCHUNK 313       // ceil(10000/32)

// ---------------- device scratch (static; no allocation allowed) ----------------
__device__ float          g_Pt[(size_t)ND * NM];           // 22.1 MB  P transposed [j][m]
__device__ __nv_bfloat16  g_Fhi[(size_t)ND * NM];          // 11 MB
__device__ __nv_bfloat16  g_Flo[(size_t)ND * NM];          // 11 MB
__device__ float          g_Bpart[(size_t)KSB * ND * ND];  // 9.8 MB
__device__ float          g_Aaug[(size_t)ND * LDA];        // [A | r] -> LU factors (rows perm'd via g_rp)
__device__ float          g_rorig[ND];
__device__ float          g_tmp[ND];                       // x0 then x1
__device__ int            g_rp[ND];                        // row permutation (logical->physical)
__device__ float          g_ld[1];
__device__ float          g_y[NM];
__device__ float          g_z[NM];
__device__ float          g_resid[ND];

// ===================== helpers ==================
__device__ __forceinline__ uint32_t smem_u32(const void* p) {
    uint32_t a;
    asm("{ .reg .u64 t; cvta.to.shared.u64 t, %1; cvt.u32.u64 %0, t; }" : "=r"(a) : "l"(p));
    return a;
}

__device__ __forceinline__ void ldx4(uint32_t* r, uint32_t addr) {
    asm volatile("ldmatrix.sync.aligned.m8n8.x4.shared.b16 {%0,%1,%2,%3}, [%4];"
                 : "=r"(r[0]), "=r"(r[1]), "=r"(r[2]), "=r"(r[3]) : "r"(addr));
}

__device__ __forceinline__ void mma16816(float* c, const uint32_t* a, uint32_t b0, uint32_t b1) {
    asm volatile(
        "mma.sync.aligned.m16n8k16.row.col.f32.bf16.bf16.f32 "
        "{%0,%1,%2,%3}, {%4,%5,%6,%7}, {%8,%9}, {%0,%1,%2,%3};"
        : "+f"(c[0]), "+f"(c[1]), "+f"(c[2]), "+f"(c[3])
        : "r"(a[0]), "r"(a[1]), "r"(a[2]), "r"(a[3]), "r"(b0), "r"(b1));
}

__device__ __forceinline__ void split2(float a, float b, uint32_t& hv, uint32_t& lv) {
    __nv_bfloat16 ha = __float2bfloat16(a), hb = __float2bfloat16(b);
    __nv_bfloat162 hh; hh.x = ha; hh.y = hb;
    hv = *(uint32_t*)&hh;
    __nv_bfloat162 ll;
    ll.x = __float2bfloat16(a - __bfloat162float(ha));
    ll.y = __float2bfloat16(b - __bfloat162float(hb));
    lv = *(uint32_t*)&ll;
}

__device__ __forceinline__ void cpasync16(uint32_t dst, const void* src, bool pred) {
    int sz = pred ? 16 : 0;
    asm volatile("cp.async.cg.shared.global [%0], [%1], 16, %2;"
                 :: "r"(dst), "l"(src), "r"(sz) : "memory");
}
#define CP_COMMIT() asm volatile("cp.async.commit_group;" ::: "memory")
#define CP_WAIT1()  asm volatile("cp.async.wait_group 1;" ::: "memory")

// per-stage layout (bytes): Ahi 0, Alo 10240, Bhi 20480, Blo 30720; stage stride 40960
#define PSTG 40960

// kBmma static layout
#define SM_BYTES 40960
#define A_LO_OFF 10240
#define B_HI_OFF 20480
#define B_LO_OFF 30720

// ============================ F -> bf16 hi/lo split ==========================
__global__ void kFsplit(const float* __restrict__ F) {
    int idx = blockIdx.x * 256 + threadIdx.x;
    if (idx >= ND * NM) return;
    float f = F[idx];
    __nv_bfloat16 h = __float2bfloat16(f);
    g_Fhi[idx] = h;
    g_Flo[idx] = __float2bfloat16(f - __bfloat162float(h));
}

// =====================================================================
// kPmma: Pt[j][m] = (s2*exp(c*D)) @ F^T  (unchanged, passing)
// =====================================================================
__global__ __launch_bounds__(256, 1) void kPmma(const float* __restrict__ Dm,
                                                const float* __restrict__ lsp,
                                                const float* __restrict__ sgp) {
    extern __shared__ __align__(16) char sm[];
    const uint32_t sb = smem_u32(sm);

    const int tid = threadIdx.x, lane = tid & 31, wid = tid >> 5;
    const int m0 = blockIdx.x * 128, j0 = blockIdx.y * 128;

    const float l = lsp[0];
    const float cexp = -0.5f / (l * l);
    const float s2 = sgp[0] * sgp[0];

    const int lr = tid >> 1, lk = (tid & 1) * 16;
    const bool mval = (m0 + lr) < NM;
    const bool nval = (j0 + lr) < ND;
    const int jrow = nval ? (j0 + lr) : (ND - 1);
    const float* Dp = Dm + (size_t)(m0 + lr) * NM + lk;
    const __nv_bfloat16* Fh = g_Fhi + (size_t)jrow * NM + lk;
    const __nv_bfloat16* Fl = g_Flo + (size_t)jrow * NM + lk;

    const uint32_t sA = (uint32_t)(lr * 40 + lk) * 2;

    float4 dv[4];
    bool dok[4];

#define LOADD(ch)                                                             \
    {                                                                         \
        int _k0 = (ch) * 32;                                                  \
        _Pragma("unroll")                                                     \
        for (int i = 0; i < 4; i++) {                                         \
            int kk = _k0 + lk + i * 4;                                        \
            dok[i] = mval && (kk < NM);                                       \
            dv[i] = dok[i] ? *(const float4*)(Dp + _k0 + i * 4)               \
                           : make_float4(0.f, 0.f, 0.f, 0.f);                 \
        }                                                                     \
    }

#define ISSUEF(ch, s)                                                         \
    {                                                                         \
        int _k0 = (ch) * 32;                                                  \
        bool ok  = nval && (_k0 + lk < NM);                                   \
        bool ok2 = nval && (_k0 + lk + 8 < NM);                               \
        uint32_t dB = sb + (s) * PSTG + 20480 + sA;                           \
        cpasync16(dB,              Fh + _k0,     ok);                         \
        cpasync16(dB + 16,         Fh + _k0 + 8, ok2);                        \
        cpasync16(dB + 10240,      Fl + _k0,     ok);                         \
        cpasync16(dB + 10240 + 16, Fl + _k0 + 8, ok2);                        \
    }

#define STSA(s)                                                               \
    {                                                                         \
        char* stg = sm + (s) * PSTG;                                          \
        _Pragma("unroll")                                                     \
        for (int i = 0; i < 4; i++) {                                         \
            float e0 = dok[i] ? s2 * __expf(cexp * dv[i].x) : 0.f;            \
            float e1 = dok[i] ? s2 * __expf(cexp * dv[i].y) : 0.f;            \
            float e2 = dok[i] ? s2 * __expf(cexp * dv[i].z) : 0.f;            \
            float e3 = dok[i] ? s2 * __expf(cexp * dv[i].w) : 0.f;            \
            uint32_t h01, l01, h23, l23;                                      \
            split2(e0, e1, h01, l01);                                         \
            split2(e2, e3, h23, l23);                                         \
            *(uint2*)(stg + sA + i * 8)         = make_uint2(h01, h23);       \
            *(uint2*)(stg + 10240 + sA + i * 8) = make_uint2(l01, l23);       \
        }                                                                     \
    }

    const int wm = (wid & 3) * 32, wn = (wid >> 2) * 64;
    const uint32_t aAoff = (uint32_t)((wm + (lane & 15)) * 40 + ((lane >> 4) & 1) * 8) * 2;
    const uint32_t aBoff = (uint32_t)((wn + ((lane >> 4) << 3) + (lane & 7)) * 40
                                      + ((lane >> 3) & 1) * 8) * 2;

    float acc[2][8][4];
#pragma unroll
    for (int a = 0; a < 2; a++)
#pragma unroll
        for (int b = 0; b < 8; b++)
#pragma unroll
            for (int d = 0; d < 4; d++) acc[a][b][d] = 0.f;

    LOADD(0);
    ISSUEF(0, 0); CP_COMMIT();
    STSA(0);
    LOADD(1);
    ISSUEF(1, 1); CP_COMMIT();
    CP_WAIT1();
    __syncthreads();

    for (int ch = 0; ch < NCHUNK; ++ch) {
        const int s = ch & 1;
        const uint32_t base = sb + s * PSTG;

#pragma unroll
        for (int kst = 0; kst < 2; ++kst) {
            uint32_t ah[2][4], al[2][4];
#pragma unroll
            for (int mt = 0; mt < 2; ++mt) {
                uint32_t o = aAoff + mt * 1280 + kst * 32;
                ldx4(ah[mt], base + o);
                ldx4(al[mt], base + 10240 + o);
            }
#pragma unroll
            for (int nh = 0; nh < 2; ++nh) {
                uint32_t bh[2][4], bl[2][4];
#pragma unroll
                for (int ng = 0; ng < 2; ++ng) {
                    uint32_t o = aBoff + nh * 2560 + ng * 1280 + kst * 32;
                    ldx4(bh[ng], base + 20480 + o);
                    ldx4(bl[ng], base + 30720 + o);
                }
#pragma unroll
                for (int mt = 0; mt < 2; mt++)
#pragma unroll
                    for (int nt = 0; nt < 4; nt++) {
                        float* cc = acc[mt][nh * 4 + nt];
                        uint32_t b0h = bh[nt >> 1][(nt & 1) * 2];
                        uint32_t b1h = bh[nt >> 1][(nt & 1) * 2 + 1];
                        uint32_t b0l = bl[nt >> 1][(nt & 1) * 2];
                        uint32_t b1l = bl[nt >> 1][(nt & 1) * 2 + 1];
                        mma16816(cc, ah[mt], b0h, b1h);
                        mma16816(cc, ah[mt], b0l, b1l);
                        mma16816(cc, al[mt], b0h, b1h);
                    }
            }
        }
        __syncthreads();

        if (ch + 2 < NCHUNK) ISSUEF(ch + 2, s);
        CP_COMMIT();
        if (ch + 1 < NCHUNK) STSA(s ^ 1);
        if (ch + 2 < NCHUNK) LOADD(ch + 2);
        CP_WAIT1();
        __syncthreads();
    }

    float* stg = (float*)sm;
#pragma unroll
    for (int h = 0; h < 2; ++h) {
        __syncthreads();
        if (((wid & 3) >> 1) == h) {
            const int rb = wm - h * 64 + (lane >> 2);
            const int cb = 2 * (lane & 3);
#pragma unroll
            for (int mt = 0; mt < 2; mt++)
#pragma unroll
                for (int nt = 0; nt < 8; nt++) {
                    int r = rb + mt * 16;
                    int c = wn + ((nt >> 2) * 32) + ((nt & 3) * 8) + cb;
                    stg[(c + 0) * 68 + r]     = acc[mt][nt][0];
                    stg[(c + 1) * 68 + r]     = acc[mt][nt][1];
                    stg[(c + 0) * 68 + r + 8] = acc[mt][nt][2];
                    stg[(c + 1) * 68 + r + 8] = acc[mt][nt][3];
                }
        }
        __syncthreads();
#pragma unroll 4
        for (int it = 0; it < 32; ++it) {
            int nr = it * 4 + (tid >> 6);
            int mc = tid & 63;
            int j = j0 + nr, m = m0 + h * 64 + mc;
            if (j < ND && m < NM) g_Pt[(size_t)j * NM + m] = stg[nr * 68 + mc];
        }
    }
}

// =====================================================================
// kBmma: Bpart[z] = F @ P   (unchanged, passing)
// =====================================================================
__global__ __launch_bounds__(256, 1) void kBmma() {
    __shared__ __align__(16) char sm[SM_BYTES];
    __nv_bfloat16* Ahi = (__nv_bfloat16*)sm;
    __nv_bfloat16* Alo = (__nv_bfloat16*)(sm + A_LO_OFF);
    __nv_bfloat16* Bhi = (__nv_bfloat16*)(sm + B_HI_OFF);
    __nv_bfloat16* Blo = (__nv_bfloat16*)(sm + B_LO_OFF);
    const uint32_t sb = smem_u32(sm);

    const int tid = threadIdx.x, lane = tid & 31, wid = tid >> 5;
    const int i0 = blockIdx.x * 128, j0 = blockIdx.y * 128;
    const int z = blockIdx.z;
    const int c0 = z * 40;
    const int c1 = min(NCHUNK, c0 + 40);

    const int lr = tid >> 1, lk = (tid & 1) * 16;
    const bool ival = (i0 + lr) < ND;
    const bool jval = (j0 + lr) < ND;
    const __nv_bfloat16* Fh = g_Fhi + (size_t)(i0 + lr) * NM + lk;
    const __nv_bfloat16* Fl = g_Flo + (size_t)(i0 + lr) * NM + lk;
    const float* Pp = g_Pt + (size_t)(j0 + lr) * NM + lk;

    float4 pv[4];
    bool pok[4];
    uint4 fh[2], fl[2];

#define LOADCH_B(k0)                                                          \
    {                                                                         \
        _Pragma("unroll")                                                     \
        for (int i = 0; i < 2; i++) {                                         \
            int kk = (k0) + lk + i * 8;                                       \
            bool ok = ival && (kk < NM);                                      \
            fh[i] = ok ? *(const uint4*)(Fh + (k0) + i * 8) : make_uint4(0, 0, 0, 0); \
            fl[i] = ok ? *(const uint4*)(Fl + (k0) + i * 8) : make_uint4(0, 0, 0, 0); \
        }                                                                     \
        _Pragma("unroll")                                                     \
        for (int i = 0; i < 4; i++) {                                         \
            int kk = (k0) + lk + i * 4;                                       \
            pok[i] = jval && (kk < NM);                                       \
            pv[i] = pok[i] ? *(const float4*)(Pp + (k0) + i * 4)              \
                           : make_float4(0.f, 0.f, 0.f, 0.f);                 \
        }                                                                     \
    }

    const int sA = lr * 40 + lk;
    const int wm = (wid & 3) * 32, wn = (wid >> 2) * 64;
    const uint32_t aAoff = (uint32_t)((wm + (lane & 15)) * 40 + ((lane >> 4) & 1) * 8) * 2;
    const uint32_t aBoff = (uint32_t)((wn + ((lane >> 4) << 3) + (lane & 7)) * 40
                                      + ((lane >> 3) & 1) * 8) * 2;

    float acc[2][8][4];
#pragma unroll
    for (int a = 0; a < 2; a++)
#pragma unroll
        for (int b = 0; b < 8; b++)
#pragma unroll
            for (int d = 0; d < 4; d++) acc[a][b][d] = 0.f;

    LOADCH_B(c0 * 32);

    for (int ch = c0; ch < c1; ++ch) {
        *(uint4*)(Ahi + sA) = fh[0];
        *(uint4*)(Ahi + sA + 8) = fh[1];
        *(uint4*)(Alo + sA) = fl[0];
        *(uint4*)(Alo + sA + 8) = fl[1];
#pragma unroll
        for (int i = 0; i < 4; i++) {
            uint32_t h01, l01, h23, l23;
            split2(pv[i].x, pv[i].y, h01, l01);
            split2(pv[i].z, pv[i].w, h23, l23);
            *(uint2*)(Bhi + sA + i * 4) = make_uint2(h01, h23);
            *(uint2*)(Blo + sA + i * 4) = make_uint2(l01, l23);
        }
        __syncthreads();

        if (ch + 1 < c1) LOADCH_B((ch + 1) * 32);

#pragma unroll
        for (int kst = 0; kst < 2; ++kst) {
            uint32_t ah[2][4], al[2][4];
#pragma unroll
            for (int mt = 0; mt < 2; ++mt) {
                uint32_t o = aAoff + mt * 1280 + kst * 32;
                ldx4(ah[mt], sb + o);
                ldx4(al[mt], sb + A_LO_OFF + o);
            }
#pragma unroll
            for (int nh = 0; nh < 2; ++nh) {
                uint32_t bh[2][4], bl[2][4];
#pragma unroll
                for (int ng = 0; ng < 2; ++ng) {
                    uint32_t o = aBoff + nh * 2560 + ng * 1280 + kst * 32;
                    ldx4(bh[ng], sb + B_HI_OFF + o);
                    ldx4(bl[ng], sb + B_LO_OFF + o);
                }
#pragma unroll
                for (int mt = 0; mt < 2; mt++)
#pragma unroll
                    for (int nt = 0; nt < 4; nt++) {
                        float* cc = acc[mt][nh * 4 + nt];
                        uint32_t b0h = bh[nt >> 1][(nt & 1) * 2];
                        uint32_t b1h = bh[nt >> 1][(nt & 1) * 2 + 1];
                        uint32_t b0l = bl[nt >> 1][(nt & 1) * 2];
                        uint32_t b1l = bl[nt >> 1][(nt & 1) * 2 + 1];
                        mma16816(cc, ah[mt], b0h, b1h);
                        mma16816(cc, ah[mt], b0l, b1l);
                        mma16816(cc, al[mt], b0h, b1h);
                    }
            }
        }
        __syncthreads();
    }

    float* Bp = g_Bpart + (size_t)z * ND * ND;
    const int rb = i0 + wm + (lane >> 2);
    const int cb = j0 + wn + 2 * (lane & 3);
#pragma unroll
    for (int mt = 0; mt < 2; mt++)
#pragma unroll
        for (int nt = 0; nt < 8; nt++) {
            int i = rb + mt * 16;
            int c = cb + (nt >> 2) * 32 + (nt & 3) * 8;
            if (c < ND) {
                if (i < ND)
                    *(float2*)(Bp + (size_t)i * ND + c) = make_float2(acc[mt][nt][0], acc[mt][nt][1]);
                if (i + 8 < ND)
                    *(float2*)(Bp + (size_t)(i + 8) * ND + c) = make_float2(acc[mt][nt][2], acc[mt][nt][3]);
            }
        }
}

// combine k-split partials + data_cov into Aaug; init row permutation
__global__ void kC(const float* __restrict__ dcov) {
    int idx = blockIdx.x * 256 + threadIdx.x;
    if (idx < ND) g_rp[idx] = idx;
    if (idx >= ND * ND) return;
    float s = dcov[idx];
#pragma unroll
    for (int zz = 0; zz < KSB; zz++) s += g_Bpart[(size_t)zz * ND * ND + idx];
    int i = idx / ND, j = idx - i * ND;
    g_Aaug[i * LDA + j] = s;
}

// prior misfit r = d_obs - m0 * rowsum(F)
__global__ __launch_bounds__(256) void kR(const float* __restrict__ F,
                                          const float* __restrict__ dobs,
                                          const float* __restrict__ m0p) {
    __shared__ float red[8];
    const int i = blockIdx.x;
    const float* row = F + (size_t)i * NM;
    float s = 0.f;
    for (int t = threadIdx.x; t < NM; t += 256) s += row[t];
#pragma unroll
    for (int o = 16; o; o >>= 1) s += __shfl_down_sync(0xffffffffu, s, o);
    if ((threadIdx.x & 31) == 0) red[threadIdx.x >> 5] = s;
    __syncthreads();
    if (threadIdx.x == 0) {
        float tot = 0.f;
#pragma unroll
        for (int w = 0; w < 8; w++) tot += red[w];
        float r = dobs[i] - m0p[0] * tot;
        g_Aaug[i * LDA + ND] = r;
        g_rorig[i] = r;
    }
}

// =====================================================================
// kLU: panel factor (perm-vector pivoting, 2 barriers/col) + fused TRSM.
// BUGFIX R13: TRSM stages L11 into zero-padded static Ls[32][33] so the
// unrolled i<32 recurrence never reads past the (nrows x pw) dynamic panel
// (last panel has nrows=8 -> sp[31*8+k] was OOB -> illegal access).
// =====================================================================
__global__ __launch_bounds__(512) void kLU(int p0, int pw) {
    extern __shared__ float dyn[];
    const int tid = threadIdx.x, lane = tid & 31, wid = tid >> 5;
    const int nrows = ND - p0;
    float* sp  = dyn;                        // nrows x pw panel
    int*   srp = (int*)(dyn + nrows * pw);   // local slice of g_rp

    __shared__ float s_pv;
    __shared__ float Ls[32][33];             // zero-padded L11 for fused TRSM

    for (int i = tid; i < nrows; i += 512) srp[i] = g_rp[p0 + i];
    __syncthreads();
    for (int idx = tid; idx < nrows * pw; idx += 512)
        sp[idx] = g_Aaug[(size_t)srp[idx / pw] * LDA + p0 + (idx % pw)];

    for (int j = 0; j < pw; j++) {
        __syncthreads();                      // panel state ready for column j
        if (wid == 0) {
            float best = -1.f; int bi = j;
            for (int i = j + lane; i < nrows; i += 32) {
                float v = fabsf(sp[i * pw + j]);
                if (v > best) { best = v; bi = i; }
            }
#pragma unroll
            for (int o = 16; o; o >>= 1) {
                float ov = __shfl_down_sync(0xffffffffu, best, o);
                int   oi = __shfl_down_sync(0xffffffffu, bi,   o);
                if (ov > best) { best = ov; bi = oi; }
            }
            int piv = __shfl_sync(0xffffffffu, bi, 0);
            if (piv != j) {
                if (lane < pw) {
                    float t = sp[j * pw + lane];
                    sp[j * pw + lane] = sp[piv * pw + lane];
                    sp[piv * pw + lane] = t;
                }
                if (lane == 0) { int t = srp[j]; srp[j] = srp[piv]; srp[piv] = t; }
            }
            __syncwarp();
            if (lane == 0) s_pv = sp[j * pw + j];
        }
        __syncthreads();                      // pivot + swap visible
        const float inv = 1.f / s_pv;
        for (int i = j + 1 + tid; i < nrows; i += 512) {
            float lij = sp[i * pw + j] * inv;
            sp[i * pw + j] = lij;
            for (int jj = j + 1; jj < pw; jj++)
                sp[i * pw + jj] -= lij * sp[j * pw + jj];
        }
    }
    __syncthreads();

    // write back panel + permutation; stage L11 into padded Ls
    for (int idx = tid; idx < 32 * 33; idx += 512) ((float*)Ls)[idx] = 0.f;
    __syncthreads();
    for (int idx = tid; idx < nrows * pw; idx += 512)
        g_Aaug[(size_t)srp[idx / pw] * LDA + p0 + (idx % pw)] = sp[idx];
    for (int i = tid; i < nrows; i += 512) g_rp[p0 + i] = srp[i];
    for (int idx = tid; idx < pw * pw; idx += 512)
        Ls[idx / pw][idx % pw] = sp[(idx / pw) * pw + (idx % pw)];
    __syncthreads();

    // fused TRSM: U12 = L11^{-1} A12 over trailing cols incl. rhs (col ND)
    for (int c = p0 + pw + tid; c <= ND; c += 512) {
        float v[32];
#pragma unroll
        for (int i = 0; i < 32; i++)
            v[i] = (i < pw) ? g_Aaug[(size_t)srp[i] * LDA + c] : 0.f;
#pragma unroll
        for (int k = 0; k < 32; k++) {
            if (k >= pw) break;
            float vk = v[k];
#pragma unroll
            for (int i = 0; i < 32; i++)
                if (i > k) v[i] -= Ls[i][k] * vk;
        }
#pragma unroll
        for (int i = 0; i < 32; i++)
            if (i < pw) g_Aaug[(size_t)srp[i] * LDA + c] = v[i];
    }
}

// A22 -= L21 @ U12  (rows via g_rp)
__global__ __launch_bounds__(256) void kG(int p0, int pw) {
    __shared__ float Ls[32][33];
    __shared__ float Us[32][36];
    __shared__ int   rmap[32];
    const int tid = threadIdx.x;
    const int r0  = p0 + pw;
    const int gi0 = r0 + blockIdx.x * 32;
    const int gj0 = r0 + blockIdx.y * 32;

    if (tid < 32) rmap[tid] = (gi0 + tid < ND) ? g_rp[gi0 + tid] : 0;
    __syncthreads();

    for (int idx = tid; idx < 32 * 32; idx += 256) {
        int i = idx >> 5, k = idx & 31;
        float v = 0.f;
        if (k < pw && gi0 + i < ND) v = g_Aaug[(size_t)rmap[i] * LDA + p0 + k];
        Ls[i][k] = v;
    }
    for (int idx = tid; idx < 32 * 32; idx += 256) {
        int k = idx >> 5, jn = idx & 31;
        float v = 0.f;
        if (k < pw && gj0 + jn <= ND) v = g_Aaug[(size_t)g_rp[p0 + k] * LDA + gj0 + jn];
        Us[k][jn] = v;
    }
    __syncthreads();

    const int mi = tid >> 3;
    const int nj = (tid & 7) * 4;
    float a0 = 0.f, a1 = 0.f, a2 = 0.f, a3 = 0.f;
    for (int k = 0; k < pw; k++) {
        float a = Ls[mi][k];
        a0 += a * Us[k][nj + 0];
        a1 += a * Us[k][nj + 1];
        a2 += a * Us[k][nj + 2];
        a3 += a * Us[k][nj + 3];
    }
    const int gi = gi0 + mi;
    if (gi < ND) {
        float* rowp = g_Aaug + (size_t)rmap[mi] * LDA;
        if (gj0 + nj + 0 <= ND) rowp[gj0 + nj + 0] -= a0;
        if (gj0 + nj + 1 <= ND) rowp[gj0 + nj + 1] -= a1;
        if (gj0 + nj + 2 <= ND) rowp[gj0 + nj + 2] -= a2;
        if (gj0 + nj + 3 <= ND) rowp[gj0 + nj + 3] -= a3;
    }
}

// back-substitution (warp-shuffle diag blocks) -> x0; logdet -> g_ld
__global__ __launch_bounds__(512) void kBack(void) {
    __shared__ float x[ND];
    __shared__ float ub[32][33];
    __shared__ float red[16];
    const int tid = threadIdx.x;

    for (int i = tid; i < ND; i += 512) x[i] = g_Aaug[(size_t)g_rp[i] * LDA + ND];
    float ld = 0.f;
    for (int k = tid; k < ND; k += 512) ld += logf(fabsf(g_Aaug[(size_t)g_rp[k] * LDA + k]));
    __syncthreads();

    for (int pb = NPANEL - 1; pb >= 0; pb--) {
        const int p0 = pb * NB;
        const int pw = (pb == NPANEL - 1) ? (ND - p0) : NB;
        for (int idx = tid; idx < pw * pw; idx += 512)
            ub[idx / pw][idx % pw] = g_Aaug[(size_t)g_rp[p0 + idx / pw] * LDA + p0 + (idx % pw)];
        __syncthreads();
        if (tid < 32) {
            float xi = (tid < pw) ? x[p0 + tid] : 0.f;
            for (int j = pw - 1; j >= 0; j--) {
                if (tid == j) xi /= ub[j][j];
                float xj = __shfl_sync(0xffffffffu, xi, j);
                if (tid < j) xi -= ub[tid][j] * xj;
            }
            if (tid < pw) x[p0 + tid] = xi;
        }
        __syncthreads();
        for (int i = tid; i < p0; i += 512) {
            float s = 0.f;
            for (int j = 0; j < pw; j++)
                s += g_Aaug[(size_t)g_rp[i] * LDA + p0 + j] * x[p0 + j];
            x[i] -= s;
        }
        __syncthreads();
    }

#pragma unroll
    for (int o = 16; o; o >>= 1) ld += __shfl_down_sync(0xffffffffu, ld, o);
    if ((tid & 31) == 0) red[tid >> 5] = ld;
    __syncthreads();
    if (tid == 0) {
        float tl = 0.f;
        for (int w = 0; w < 16; w++) tl += red[w];
        g_ld[0] = tl;
    }
    for (int i = tid; i < ND; i += 512) g_tmp[i] = x[i];
}

// ===================== iterative refinement: exact fp32 operator =============
__global__ __launch_bounds__(256) void kAy(const float* __restrict__ F) {
    __shared__ float sx[ND];
    const int tid = threadIdx.x;
    for (int i = tid; i < ND; i += 256) sx[i] = g_tmp[i];
    __syncthreads();
    const int m = blockIdx.x * 256 + tid;
    if (m >= NM) return;
    float s = 0.f;
#pragma unroll 4
    for (int i = 0; i < ND; i++) s += F[(size_t)i * NM + m] * sx[i];
    g_y[m] = s;
}

__global__ __launch_bounds__(256) void kAz(const float* __restrict__ Dm,
                                           const float* __restrict__ lsp,
                                           const float* __restrict__ sgp) {
    const int tid = threadIdx.x, lane = tid & 31, warp = tid >> 5;
    const int row = blockIdx.x * 8 + warp;
    if (row >= NM) return;
    const float l = lsp[0];
    const float c = -0.5f / (l * l);
    const float s2 = sgp[0] * sgp[0];
    const float* dr = Dm + (size_t)row * NM;
    float s = 0.f;
    for (int k = lane; k < NM; k += 32) s += __expf(c * dr[k]) * __ldg(&g_y[k]);
#pragma unroll
    for (int o = 16; o; o >>= 1) s += __shfl_down_sync(0xffffffffu, s, o);
    if (lane == 0) g_z[row] = s2 * s;
}

__global__ __launch_bounds__(256) void kAw(const float* __restrict__ F,
                                           const float* __restrict__ dcov) {
    __shared__ float red[8];
    const int i = blockIdx.x;
    const int tid = threadIdx.x;
    float s = 0.f;
    const float* fr = F + (size_t)i * NM;
    for (int m = tid; m < NM; m += 256) s += fr[m] * g_z[m];
    const float* cr = dcov + (size_t)i * ND;
    for (int j = tid; j < ND; j += 256) s += cr[j] * g_tmp[j];
#pragma unroll
    for (int o = 16; o; o >>= 1) s += __shfl_down_sync(0xffffffffu, s, o);
    if ((tid & 31) == 0) red[tid >> 5] = s;
    __syncthreads();
    if (tid == 0) {
        float tot = 0.f;
#pragma unroll
        for (int w = 0; w < 8; w++) tot += red[w];
        g_resid[i] = g_rorig[i] - tot;
    }
}

// solve LU dx = P resid; x1 = x0 + dx; out[0] = logdet + r^T x1; g_tmp = x1
__global__ __launch_bounds__(512) void kSolve(float* __restrict__ out) {
    __shared__ float x[ND];
    __shared__ float Bs[32][33];
    __shared__ float red[16];
    const int tid = threadIdx.x;

    // parallel permuted gather: (P r)[k] = resid[rp[k]]
    for (int i = tid; i < ND; i += 512) x[i] = g_resid[g_rp[i]];
    __syncthreads();

    // forward: L (unit diag)
    for (int pb = 0; pb < NPANEL; pb++) {
        const int p0 = pb * NB;
        const int pw = (pb == NPANEL - 1) ? (ND - p0) : NB;
        for (int idx = tid; idx < pw * pw; idx += 512)
            Bs[idx / pw][idx % pw] = g_Aaug[(size_t)g_rp[p0 + idx / pw] * LDA + p0 + (idx % pw)];
        __syncthreads();
        if (tid < 32) {
            float xi = (tid < pw) ? x[p0 + tid] : 0.f;
            for (int j = 0; j < pw; j++) {
                float xj = __shfl_sync(0xffffffffu, xi, j);
                if (tid > j && tid < pw) xi -= Bs[tid][j] * xj;
            }
            if (tid < pw) x[p0 + tid] = xi;
        }
        __syncthreads();
        for (int i = p0 + pw + tid; i < ND; i += 512) {
            float s = 0.f;
            for (int j = 0; j < pw; j++)
                s += g_Aaug[(size_t)g_rp[i] * LDA + p0 + j] * x[p0 + j];
            x[i] -= s;
        }
        __syncthreads();
    }

    // backward: U
    for (int pb = NPANEL - 1; pb >= 0; pb--) {
        const int p0 = pb * NB;
        const int pw = (pb == NPANEL - 1) ? (ND - p0) : NB;
        for (int idx = tid; idx < pw * pw; idx += 512)
            Bs[idx / pw][idx % pw] = g_Aaug[(size_t)g_rp[p0 + idx / pw] * LDA + p0 + (idx % pw)];
        __syncthreads();
        if (tid < 32) {
            float xi = (tid < pw) ? x[p0 + tid] : 0.f;
            for (int j = pw - 1; j >= 0; j--) {
                if (tid == j) xi /= Bs[j][j];
                float xj = __shfl_sync(0xffffffffu, xi, j);
                if (tid < j) xi -= Bs[tid][j] * xj;
            }
            if (tid < pw) x[p0 + tid] = xi;
        }
        __syncthreads();
        for (int i = tid; i < p0; i += 512) {
            float s = 0.f;
            for (int j = 0; j < pw; j++)
                s += g_Aaug[(size_t)g_rp[i] * LDA + p0 + j] * x[p0 + j];
            x[i] -= s;
        }
        __syncthreads();
    }

    // x1 = x0 + dx; dp = r^T x1
    float dp = 0.f;
    for (int i = tid; i < ND; i += 512) {
        float v = g_tmp[i] + x[i];
        x[i] = v;
        dp += g_rorig[i] * v;
    }
#pragma unroll
    for (int o = 16; o; o >>= 1) dp += __shfl_down_sync(0xffffffffu, dp, o);
    if ((tid & 31) == 0) red[tid >> 5] = dp;
    __syncthreads();
    if (tid == 0) {
        float td = 0.f;
#pragma unroll
        for (int w = 0; w < 16; w++) td += red[w];
        out[0] = g_ld[0] + td;
    }
    for (int i = tid; i < ND; i += 512) g_tmp[i] = x[i];
}

// m_posterior = m0 + P @ x1, via Pt (thread per model row, coalesced)
__global__ __launch_bounds__(256) void kM(float* __restrict__ out,
                                          const float* __restrict__ m0p) {
    __shared__ float sx[ND];
    const int tid = threadIdx.x;
    for (int i = tid; i < ND; i += 256) sx[i] = g_tmp[i];
    __syncthreads();
    const int m = blockIdx.x * 256 + tid;
    if (m >= NM) return;
    float s = 0.f;
#pragma unroll 4
    for (int j = 0; j < ND; j++) s += g_Pt[(size_t)j * NM + m] * sx[j];
    out[1 + m] = m0p[0] + s;
}

// =====================================================================
extern "C" void kernel_launch(void* const* d_in, const int* in_sizes, int n_in,
                              void* d_out, int out_size) {
    const float* D    = (const float*)d_in[0];
    const float* F    = (const float*)d_in[1];
    const float* dobs = (const float*)d_in[2];
    const float* dcov = (const float*)d_in[3];
    const float* m0p  = (const float*)d_in[4];
    const float* lsp  = (const float*)d_in[5];
    const float* sgp  = (const float*)d_in[6];
    float* out = (float*)d_out;

    cudaFuncSetAttribute(kLU, cudaFuncAttributeMaxDynamicSharedMemorySize,
                         ND * NB * 4 + ND * 4);
    cudaFuncSetAttribute(kPmma, cudaFuncAttributeMaxDynamicSharedMemorySize, 2 * PSTG);

    kFsplit<<<(ND * NM + 255) / 256, 256>>>(F);
    kPmma<<<dim3(79, 5), 256, 2 * PSTG>>>(D, lsp, sgp);
    kBmma<<<dim3(5, 5, KSB), 256>>>();
    kC<<<(ND * ND + 255) / 256, 256>>>(dcov);
    kR<<<ND, 256>>>(F, dobs, m0p);

    for (int p = 0; p < NPANEL; p++) {
        const int p0 = p * NB;
        const int pw = (p == NPANEL - 1) ? (ND - p0) : NB;
        const int nrows = ND - p0;
        kLU<<<1, 512, nrows * pw * 4 + nrows * 4>>>(p0, pw);
        const int m = ND - (p0 + pw);
        const int tcols = ND + 1 - (p0 + pw);
        if (m > 0)
            kG<<<dim3((m + 31) / 32, (tcols + 31) / 32), 256>>>(p0, pw);
    }

    kBack<<<1, 512>>>();
    kAy<<<(NM + 255) / 256, 256>>>(F);
    kAz<<<(NM + 7) / 8, 256>>>(D, lsp, sgp);
    kAw<<<ND, 256>>>(F, dcov);
    kSolve<<<1, 512>>>(out);
    kM<<<(NM + 255) / 256, 256>>>(out, m0p);
}